// round 1
// baseline (speedup 1.0000x reference)
#include <cuda_runtime.h>
#include <math.h>

#define B_    2
#define S_    2048
#define DM    1024
#define H_    16
#define DH    64
#define DFF   4096
#define MTOK  (B_*S_)      // 4096 token rows

// ---------------- scratch (device globals; no allocation) ----------------
__device__ float g_Q[MTOK*DM];
__device__ float g_K[MTOK*DM];
__device__ float g_V[MTOK*DM];
__device__ float g_att[MTOK*DM];
__device__ float g_x[MTOK*DM];
__device__ float g_h[(size_t)MTOK*DFF];

// ---------------- tiled SGEMM, NT layout: C[m,n] = sum_k A[m,k]*B[n,k] ----
// EPI: 0 = +bias, 1 = gelu(+bias) exact, 2 = +bias + res[m,n]
template<int EPI>
__global__ __launch_bounds__(256)
void gemm_nt(const float* __restrict__ A, const float* __restrict__ Bm,
             const float* __restrict__ bias, float* __restrict__ C,
             const float* __restrict__ res, int M, int N, int K)
{
    __shared__ float As[16][132];
    __shared__ float Bs[16][132];

    const int tid = threadIdx.x;
    const int m0 = blockIdx.y * 128;
    const int n0 = blockIdx.x * 128;
    const int ty = tid >> 4;       // 0..15
    const int tx = tid & 15;       // 0..15

    float acc[8][8];
    #pragma unroll
    for (int i = 0; i < 8; i++)
        #pragma unroll
        for (int j = 0; j < 8; j++) acc[i][j] = 0.f;

    for (int k0 = 0; k0 < K; k0 += 16) {
        // load 128x16 A tile and 128x16 B tile (transposed into smem)
        #pragma unroll
        for (int i = 0; i < 2; i++) {
            int lin = tid + i * 256;         // 0..511 float4 slots
            int row = lin >> 2;              // 0..127
            int c   = (lin & 3) * 4;         // 0,4,8,12
            float4 fa = *(const float4*)&A [(size_t)(m0 + row) * K + k0 + c];
            As[c + 0][row] = fa.x; As[c + 1][row] = fa.y;
            As[c + 2][row] = fa.z; As[c + 3][row] = fa.w;
            float4 fb = *(const float4*)&Bm[(size_t)(n0 + row) * K + k0 + c];
            Bs[c + 0][row] = fb.x; Bs[c + 1][row] = fb.y;
            Bs[c + 2][row] = fb.z; Bs[c + 3][row] = fb.w;
        }
        __syncthreads();

        #pragma unroll
        for (int kk = 0; kk < 16; kk++) {
            float a[8], b[8];
            float4 t;
            t = *(const float4*)&As[kk][ty * 8 + 0]; a[0]=t.x; a[1]=t.y; a[2]=t.z; a[3]=t.w;
            t = *(const float4*)&As[kk][ty * 8 + 4]; a[4]=t.x; a[5]=t.y; a[6]=t.z; a[7]=t.w;
            t = *(const float4*)&Bs[kk][tx * 8 + 0]; b[0]=t.x; b[1]=t.y; b[2]=t.z; b[3]=t.w;
            t = *(const float4*)&Bs[kk][tx * 8 + 4]; b[4]=t.x; b[5]=t.y; b[6]=t.z; b[7]=t.w;
            #pragma unroll
            for (int i = 0; i < 8; i++)
                #pragma unroll
                for (int j = 0; j < 8; j++)
                    acc[i][j] = fmaf(a[i], b[j], acc[i][j]);
        }
        __syncthreads();
    }

    // epilogue
    #pragma unroll
    for (int i = 0; i < 8; i++) {
        const int m = m0 + ty * 8 + i;
        #pragma unroll
        for (int j = 0; j < 8; j += 4) {
            const int n = n0 + tx * 8 + j;
            float v[4];
            #pragma unroll
            for (int u = 0; u < 4; u++) {
                float t = acc[i][j + u] + bias[n + u];
                if (EPI == 1) {
                    t = 0.5f * t * (1.0f + erff(t * 0.70710678118654752f));
                } else if (EPI == 2) {
                    t += res[(size_t)m * N + n + u];
                }
                v[u] = t;
            }
            float4 o; o.x = v[0]; o.y = v[1]; o.z = v[2]; o.w = v[3];
            *(float4*)&C[(size_t)m * N + n] = o;
        }
    }
}

// ---------------- causal flash attention (fp32, 1 thread = 1 q row) ------
__global__ __launch_bounds__(128)
void attn_kernel(const float* __restrict__ Q, const float* __restrict__ K,
                 const float* __restrict__ V, float* __restrict__ O,
                 const int* __restrict__ use_mask)
{
    __shared__ float Ks[64 * 64];
    __shared__ float Vs[64 * 64];

    const int tid = threadIdx.x;
    const int qb  = blockIdx.x;   // 16 q-blocks of 128 rows
    const int h   = blockIdx.y;
    const int b   = blockIdx.z;
    const int qi  = qb * 128 + tid;
    const int causal = use_mask[0];

    float qreg[64];
    {
        const float4* qp = (const float4*)&Q[((size_t)(b * S_ + qi)) * DM + h * DH];
        #pragma unroll
        for (int i = 0; i < 16; i++) {
            float4 f = qp[i];
            qreg[4*i+0] = f.x; qreg[4*i+1] = f.y; qreg[4*i+2] = f.z; qreg[4*i+3] = f.w;
        }
    }

    float m = -INFINITY, l = 0.f;
    float acc[64];
    #pragma unroll
    for (int d = 0; d < 64; d++) acc[d] = 0.f;

    const int kb_end = causal ? (qb * 2 + 2) : (S_ / 64);
    for (int kb = 0; kb < kb_end; kb++) {
        // stage 64 keys + 64 values into smem
        #pragma unroll
        for (int i = 0; i < 8; i++) {
            int lin = tid + i * 128;          // 0..1023 float4 slots
            int row = lin >> 4;               // 0..63
            int c   = (lin & 15) * 4;         // 0..60
            size_t src = ((size_t)(b * S_ + kb * 64 + row)) * DM + h * DH + c;
            *(float4*)&Ks[row * 64 + c] = *(const float4*)&K[src];
            *(float4*)&Vs[row * 64 + c] = *(const float4*)&V[src];
        }
        __syncthreads();

        int jlim = 64;
        if (causal) {
            int rel = qi - kb * 64 + 1;
            jlim = rel < 64 ? rel : 64;
            if (jlim < 0) jlim = 0;
        }
        for (int j = 0; j < jlim; j++) {
            const float4* kr = (const float4*)&Ks[j * 64];
            float s = 0.f;
            #pragma unroll
            for (int i = 0; i < 16; i++) {
                float4 f = kr[i];
                s = fmaf(qreg[4*i+0], f.x, s);
                s = fmaf(qreg[4*i+1], f.y, s);
                s = fmaf(qreg[4*i+2], f.z, s);
                s = fmaf(qreg[4*i+3], f.w, s);
            }
            s *= 0.125f;  // 1/sqrt(64)
            if (s > m) {
                float corr = __expf(m - s);
                m = s;
                l *= corr;
                #pragma unroll
                for (int d = 0; d < 64; d++) acc[d] *= corr;
            }
            float p = __expf(s - m);
            l += p;
            const float4* vr = (const float4*)&Vs[j * 64];
            #pragma unroll
            for (int i = 0; i < 16; i++) {
                float4 f = vr[i];
                acc[4*i+0] = fmaf(p, f.x, acc[4*i+0]);
                acc[4*i+1] = fmaf(p, f.y, acc[4*i+1]);
                acc[4*i+2] = fmaf(p, f.z, acc[4*i+2]);
                acc[4*i+3] = fmaf(p, f.w, acc[4*i+3]);
            }
        }
        __syncthreads();
    }

    const float inv = 1.f / l;
    float4* op = (float4*)&O[((size_t)(b * S_ + qi)) * DM + h * DH];
    #pragma unroll
    for (int i = 0; i < 16; i++) {
        float4 f;
        f.x = acc[4*i+0] * inv; f.y = acc[4*i+1] * inv;
        f.z = acc[4*i+2] * inv; f.w = acc[4*i+3] * inv;
        op[i] = f;
    }
}

// ---------------- residual add + layernorm (one row per CTA) -------------
__global__ __launch_bounds__(256)
void ln_kernel(const float* __restrict__ att, const float* __restrict__ resid,
               const float* __restrict__ g, const float* __restrict__ bt,
               float* __restrict__ xout)
{
    const int row = blockIdx.x;
    const int tid = threadIdx.x;

    float4 a = *(const float4*)&att  [(size_t)row * DM + tid * 4];
    float4 r = *(const float4*)&resid[(size_t)row * DM + tid * 4];
    float4 v;
    v.x = a.x + r.x; v.y = a.y + r.y; v.z = a.z + r.z; v.w = a.w + r.w;

    float s1 = v.x + v.y + v.z + v.w;
    float s2 = v.x*v.x + v.y*v.y + v.z*v.z + v.w*v.w;

    __shared__ float sh1[8], sh2[8];
    #pragma unroll
    for (int o = 16; o > 0; o >>= 1) {
        s1 += __shfl_xor_sync(0xffffffffu, s1, o);
        s2 += __shfl_xor_sync(0xffffffffu, s2, o);
    }
    if ((tid & 31) == 0) { sh1[tid >> 5] = s1; sh2[tid >> 5] = s2; }
    __syncthreads();
    float t1 = 0.f, t2 = 0.f;
    #pragma unroll
    for (int i = 0; i < 8; i++) { t1 += sh1[i]; t2 += sh2[i]; }

    const float mu  = t1 * (1.0f / DM);
    const float var = t2 * (1.0f / DM) - mu * mu;
    const float rs  = rsqrtf(var + 1e-5f);

    float4 gg = *(const float4*)&g [tid * 4];
    float4 bb = *(const float4*)&bt[tid * 4];
    float4 o;
    o.x = (v.x - mu) * rs * gg.x + bb.x;
    o.y = (v.y - mu) * rs * gg.y + bb.y;
    o.z = (v.z - mu) * rs * gg.z + bb.z;
    o.w = (v.w - mu) * rs * gg.w + bb.w;
    *(float4*)&xout[(size_t)row * DM + tid * 4] = o;
}

// ---------------- launch ---------------------------------------------------
extern "C" void kernel_launch(void* const* d_in, const int* in_sizes, int n_in,
                              void* d_out, int out_size)
{
    const float* q    = (const float*)d_in[0];
    const float* k    = (const float*)d_in[1];
    const float* Wq   = (const float*)d_in[2];
    const float* bq   = (const float*)d_in[3];
    const float* Wk   = (const float*)d_in[4];
    const float* bk   = (const float*)d_in[5];
    const float* Wv   = (const float*)d_in[6];
    const float* bv   = (const float*)d_in[7];
    const float* W1   = (const float*)d_in[8];
    const float* b1   = (const float*)d_in[9];
    const float* W2   = (const float*)d_in[10];
    const float* b2   = (const float*)d_in[11];
    const float* ln_g = (const float*)d_in[12];
    const float* ln_b = (const float*)d_in[13];
    const int*   msk  = (const int*)d_in[14];

    float *Qb, *Kb, *Vb, *Ab, *Xb, *Hb;
    cudaGetSymbolAddress((void**)&Qb, g_Q);
    cudaGetSymbolAddress((void**)&Kb, g_K);
    cudaGetSymbolAddress((void**)&Vb, g_V);
    cudaGetSymbolAddress((void**)&Ab, g_att);
    cudaGetSymbolAddress((void**)&Xb, g_x);
    cudaGetSymbolAddress((void**)&Hb, g_h);

    // QKV projections: [4096,1024] @ [1024,1024]^T
    gemm_nt<0><<<dim3(DM / 128, MTOK / 128), 256>>>(q, Wq, bq, Qb, nullptr, MTOK, DM, DM);
    gemm_nt<0><<<dim3(DM / 128, MTOK / 128), 256>>>(k, Wk, bk, Kb, nullptr, MTOK, DM, DM);
    gemm_nt<0><<<dim3(DM / 128, MTOK / 128), 256>>>(k, Wv, bv, Vb, nullptr, MTOK, DM, DM);

    // causal attention
    attn_kernel<<<dim3(S_ / 128, H_, B_), 128>>>(Qb, Kb, Vb, Ab, msk);

    // residual + layernorm
    ln_kernel<<<MTOK, 256>>>(Ab, q, ln_g, ln_b, Xb);

    // FFN: gelu(x @ W1^T + b1) @ W2^T + b2 + x
    gemm_nt<1><<<dim3(DFF / 128, MTOK / 128), 256>>>(Xb, W1, b1, Hb, nullptr, MTOK, DFF, DM);
    gemm_nt<2><<<dim3(DM / 128, MTOK / 128), 256>>>(Hb, W2, b2, (float*)d_out, Xb, MTOK, DM, DFF);
}

// round 2
// speedup vs baseline: 1.2771x; 1.2771x over previous
#include <cuda_runtime.h>
#include <math.h>

#define B_    2
#define S_    2048
#define DM    1024
#define H_    16
#define DH    64
#define DFF   4096
#define MTOK  (B_*S_)      // 4096 token rows

// ---------------- scratch (device globals; no allocation) ----------------
__device__ float g_Q[MTOK*DM];
__device__ float g_K[MTOK*DM];
__device__ float g_V[MTOK*DM];
__device__ float g_att[MTOK*DM];
__device__ float g_x[MTOK*DM];
__device__ float g_h[(size_t)MTOK*DFF];

// ---------------- tf32 helpers -------------------------------------------
__device__ __forceinline__ float f2tf32(float x) {
    unsigned r;
    asm("cvt.rna.tf32.f32 %0, %1;" : "=r"(r) : "f"(x));
    return __uint_as_float(r);
}

__device__ __forceinline__ void mma_tf32(float c[4],
                                         unsigned a0, unsigned a1, unsigned a2, unsigned a3,
                                         unsigned b0, unsigned b1) {
    asm volatile("mma.sync.aligned.m16n8k8.row.col.f32.tf32.tf32.f32 "
                 "{%0,%1,%2,%3}, {%4,%5,%6,%7}, {%8,%9}, {%0,%1,%2,%3};"
                 : "+f"(c[0]), "+f"(c[1]), "+f"(c[2]), "+f"(c[3])
                 : "r"(a0), "r"(a1), "r"(a2), "r"(a3), "r"(b0), "r"(b1));
}

// ---------------- tensor-core GEMM (tf32), NT: C[m,n] = sum_k A[m,k]B[n,k]
// Tile 128x128, Kc=16, double-buffered. 8 warps: 2(m) x 4(n), warp tile 64x32.
// EPI: 0 = +bias, 1 = gelu(+bias) exact, 2 = +bias + res
#define KC 16
#define LDS_PITCH 20   // 16 + 4 pad: conflict-free fragment loads

template<int EPI>
__global__ __launch_bounds__(256)
void gemm_tc(const float* __restrict__ A, const float* __restrict__ Bm,
             const float* __restrict__ bias, float* __restrict__ C,
             const float* __restrict__ res, int M, int N, int K)
{
    __shared__ float As[2][128 * LDS_PITCH];
    __shared__ float Bs[2][128 * LDS_PITCH];

    const int tid  = threadIdx.x;
    const int m0   = blockIdx.y * 128;
    const int n0   = blockIdx.x * 128;
    const int lane = tid & 31;
    const int w    = tid >> 5;
    const int wm   = (w >> 2) * 64;   // warp row offset (0 or 64)
    const int wn   = (w & 3) * 32;    // warp col offset
    const int g    = lane >> 2;       // 0..7
    const int t    = lane & 3;        // 0..3

    float acc[4][4][4];
    #pragma unroll
    for (int i = 0; i < 4; i++)
        #pragma unroll
        for (int j = 0; j < 4; j++)
            #pragma unroll
            for (int u = 0; u < 4; u++) acc[i][j][u] = 0.f;

    // staging registers: 2 float4 for A, 2 for B per thread
    float4 ra[2], rb[2];
    const int srow0 = tid >> 2;          // idx = tid       -> row, c4
    const int sc40  = tid & 3;
    const int srow1 = (tid + 256) >> 2;  // idx = tid + 256
    const int sc41  = (tid + 256) & 3;

    auto gload = [&](int k0) {
        ra[0] = *(const float4*)&A [(size_t)(m0 + srow0) * K + k0 + sc40 * 4];
        rb[0] = *(const float4*)&Bm[(size_t)(n0 + srow0) * K + k0 + sc40 * 4];
        ra[1] = *(const float4*)&A [(size_t)(m0 + srow1) * K + k0 + sc41 * 4];
        rb[1] = *(const float4*)&Bm[(size_t)(n0 + srow1) * K + k0 + sc41 * 4];
    };
    auto sts = [&](int buf) {
        float4 v;
        v.x = f2tf32(ra[0].x); v.y = f2tf32(ra[0].y); v.z = f2tf32(ra[0].z); v.w = f2tf32(ra[0].w);
        *(float4*)&As[buf][srow0 * LDS_PITCH + sc40 * 4] = v;
        v.x = f2tf32(rb[0].x); v.y = f2tf32(rb[0].y); v.z = f2tf32(rb[0].z); v.w = f2tf32(rb[0].w);
        *(float4*)&Bs[buf][srow0 * LDS_PITCH + sc40 * 4] = v;
        v.x = f2tf32(ra[1].x); v.y = f2tf32(ra[1].y); v.z = f2tf32(ra[1].z); v.w = f2tf32(ra[1].w);
        *(float4*)&As[buf][srow1 * LDS_PITCH + sc41 * 4] = v;
        v.x = f2tf32(rb[1].x); v.y = f2tf32(rb[1].y); v.z = f2tf32(rb[1].z); v.w = f2tf32(rb[1].w);
        *(float4*)&Bs[buf][srow1 * LDS_PITCH + sc41 * 4] = v;
    };
    auto compute = [&](int buf) {
        #pragma unroll
        for (int kk = 0; kk < KC; kk += 8) {
            unsigned af[4][4], bf[4][2];
            #pragma unroll
            for (int mt = 0; mt < 4; mt++) {
                int r = wm + mt * 16 + g;
                af[mt][0] = __float_as_uint(As[buf][(r    ) * LDS_PITCH + kk + t    ]);
                af[mt][1] = __float_as_uint(As[buf][(r + 8) * LDS_PITCH + kk + t    ]);
                af[mt][2] = __float_as_uint(As[buf][(r    ) * LDS_PITCH + kk + t + 4]);
                af[mt][3] = __float_as_uint(As[buf][(r + 8) * LDS_PITCH + kk + t + 4]);
            }
            #pragma unroll
            for (int nt = 0; nt < 4; nt++) {
                int r = wn + nt * 8 + g;
                bf[nt][0] = __float_as_uint(Bs[buf][r * LDS_PITCH + kk + t    ]);
                bf[nt][1] = __float_as_uint(Bs[buf][r * LDS_PITCH + kk + t + 4]);
            }
            #pragma unroll
            for (int mt = 0; mt < 4; mt++)
                #pragma unroll
                for (int nt = 0; nt < 4; nt++)
                    mma_tf32(acc[mt][nt], af[mt][0], af[mt][1], af[mt][2], af[mt][3],
                             bf[nt][0], bf[nt][1]);
        }
    };

    const int NC = K / KC;
    gload(0);
    sts(0);
    __syncthreads();
    for (int c = 0; c < NC; c++) {
        if (c + 1 < NC) gload((c + 1) * KC);
        compute(c & 1);
        if (c + 1 < NC) sts((c + 1) & 1);
        __syncthreads();
    }

    // epilogue
    #pragma unroll
    for (int mt = 0; mt < 4; mt++) {
        #pragma unroll
        for (int half = 0; half < 2; half++) {
            const int row = m0 + wm + mt * 16 + g + half * 8;
            #pragma unroll
            for (int nt = 0; nt < 4; nt++) {
                const int col = n0 + wn + nt * 8 + 2 * t;
                float v0 = acc[mt][nt][half * 2 + 0] + bias[col];
                float v1 = acc[mt][nt][half * 2 + 1] + bias[col + 1];
                if (EPI == 1) {
                    v0 = 0.5f * v0 * (1.0f + erff(v0 * 0.70710678118654752f));
                    v1 = 0.5f * v1 * (1.0f + erff(v1 * 0.70710678118654752f));
                } else if (EPI == 2) {
                    v0 += res[(size_t)row * N + col];
                    v1 += res[(size_t)row * N + col + 1];
                }
                float2 o; o.x = v0; o.y = v1;
                *(float2*)&C[(size_t)row * N + col] = o;
            }
        }
    }
}

// ---------------- causal flash attention (fp32, 2 threads per q row) -----
__global__ __launch_bounds__(256)
void attn_kernel(const float* __restrict__ Q, const float* __restrict__ K,
                 const float* __restrict__ V, float* __restrict__ O,
                 const int* __restrict__ use_mask)
{
    __shared__ float Ks[64 * 64];
    __shared__ float Vs[64 * 64];

    const int tid  = threadIdx.x;
    const int rowl = tid >> 1;           // local q row 0..127
    const int half = tid & 1;            // which 32-dim half
    const int wid  = tid >> 5;           // warp 0..7 -> rows wid*16..+15
    const int qb   = (gridDim.x - 1) - blockIdx.x;   // heavy blocks first
    const int h    = blockIdx.y;
    const int b    = blockIdx.z;
    const int qi   = qb * 128 + rowl;
    const int causal = use_mask[0];

    float qreg[32];
    {
        const float4* qp = (const float4*)&Q[((size_t)(b * S_ + qi)) * DM + h * DH + half * 32];
        #pragma unroll
        for (int i = 0; i < 8; i++) {
            float4 f = qp[i];
            qreg[4*i+0] = f.x; qreg[4*i+1] = f.y; qreg[4*i+2] = f.z; qreg[4*i+3] = f.w;
        }
    }

    float m = -INFINITY, l = 0.f;
    float acc[32];
    #pragma unroll
    for (int d = 0; d < 32; d++) acc[d] = 0.f;

    const int kb_end = causal ? (qb * 2 + 2) : (S_ / 64);
    for (int kb = 0; kb < kb_end; kb++) {
        // stage 64 keys + 64 values (each 64 floats) into smem
        #pragma unroll
        for (int i = 0; i < 4; i++) {
            int lin = tid + i * 256;          // 0..1023 float4 slots
            int row = lin >> 4;               // 0..63
            int c   = (lin & 15) * 4;
            size_t src = ((size_t)(b * S_ + kb * 64 + row)) * DM + h * DH + c;
            *(float4*)&Ks[row * 64 + c] = *(const float4*)&K[src];
            *(float4*)&Vs[row * 64 + c] = *(const float4*)&V[src];
        }
        __syncthreads();

        // per-thread valid limit; warp-uniform loop bound (keeps shfl converged)
        int jlim = 64, jub = 64;
        if (causal) {
            int rel = qi - kb * 64 + 1;
            jlim = rel < 64 ? rel : 64;
            int qimax = qb * 128 + wid * 16 + 15;
            int relw  = qimax - kb * 64 + 1;
            jub = relw < 64 ? relw : 64;
            if (jub < 0) jub = 0;
        }
        for (int j = 0; j < jub; j++) {
            const float4* kr = (const float4*)&Ks[j * 64 + half * 32];
            float s = 0.f;
            #pragma unroll
            for (int i = 0; i < 8; i++) {
                float4 f = kr[i];
                s = fmaf(qreg[4*i+0], f.x, s);
                s = fmaf(qreg[4*i+1], f.y, s);
                s = fmaf(qreg[4*i+2], f.z, s);
                s = fmaf(qreg[4*i+3], f.w, s);
            }
            s += __shfl_xor_sync(0xffffffffu, s, 1);
            s *= 0.125f;  // 1/sqrt(64)
            if (j < jlim) {
                if (s > m) {
                    float corr = __expf(m - s);
                    m = s;
                    l *= corr;
                    #pragma unroll
                    for (int d = 0; d < 32; d++) acc[d] *= corr;
                }
                float p = __expf(s - m);
                l += p;
                const float4* vr = (const float4*)&Vs[j * 64 + half * 32];
                #pragma unroll
                for (int i = 0; i < 8; i++) {
                    float4 f = vr[i];
                    acc[4*i+0] = fmaf(p, f.x, acc[4*i+0]);
                    acc[4*i+1] = fmaf(p, f.y, acc[4*i+1]);
                    acc[4*i+2] = fmaf(p, f.z, acc[4*i+2]);
                    acc[4*i+3] = fmaf(p, f.w, acc[4*i+3]);
                }
            }
        }
        __syncthreads();
    }

    const float inv = 1.f / l;
    float4* op = (float4*)&O[((size_t)(b * S_ + qi)) * DM + h * DH + half * 32];
    #pragma unroll
    for (int i = 0; i < 8; i++) {
        float4 f;
        f.x = acc[4*i+0] * inv; f.y = acc[4*i+1] * inv;
        f.z = acc[4*i+2] * inv; f.w = acc[4*i+3] * inv;
        op[i] = f;
    }
}

// ---------------- residual add + layernorm (one row per CTA) -------------
__global__ __launch_bounds__(256)
void ln_kernel(const float* __restrict__ att, const float* __restrict__ resid,
               const float* __restrict__ g, const float* __restrict__ bt,
               float* __restrict__ xout)
{
    const int row = blockIdx.x;
    const int tid = threadIdx.x;

    float4 a = *(const float4*)&att  [(size_t)row * DM + tid * 4];
    float4 r = *(const float4*)&resid[(size_t)row * DM + tid * 4];
    float4 v;
    v.x = a.x + r.x; v.y = a.y + r.y; v.z = a.z + r.z; v.w = a.w + r.w;

    float s1 = v.x + v.y + v.z + v.w;
    float s2 = v.x*v.x + v.y*v.y + v.z*v.z + v.w*v.w;

    __shared__ float sh1[8], sh2[8];
    #pragma unroll
    for (int o = 16; o > 0; o >>= 1) {
        s1 += __shfl_xor_sync(0xffffffffu, s1, o);
        s2 += __shfl_xor_sync(0xffffffffu, s2, o);
    }
    if ((tid & 31) == 0) { sh1[tid >> 5] = s1; sh2[tid >> 5] = s2; }
    __syncthreads();
    float t1 = 0.f, t2 = 0.f;
    #pragma unroll
    for (int i = 0; i < 8; i++) { t1 += sh1[i]; t2 += sh2[i]; }

    const float mu  = t1 * (1.0f / DM);
    const float var = t2 * (1.0f / DM) - mu * mu;
    const float rs  = rsqrtf(var + 1e-5f);

    float4 gg = *(const float4*)&g [tid * 4];
    float4 bb = *(const float4*)&bt[tid * 4];
    float4 o;
    o.x = (v.x - mu) * rs * gg.x + bb.x;
    o.y = (v.y - mu) * rs * gg.y + bb.y;
    o.z = (v.z - mu) * rs * gg.z + bb.z;
    o.w = (v.w - mu) * rs * gg.w + bb.w;
    *(float4*)&xout[(size_t)row * DM + tid * 4] = o;
}

// ---------------- launch ---------------------------------------------------
extern "C" void kernel_launch(void* const* d_in, const int* in_sizes, int n_in,
                              void* d_out, int out_size)
{
    const float* q    = (const float*)d_in[0];
    const float* k    = (const float*)d_in[1];
    const float* Wq   = (const float*)d_in[2];
    const float* bq   = (const float*)d_in[3];
    const float* Wk   = (const float*)d_in[4];
    const float* bk   = (const float*)d_in[5];
    const float* Wv   = (const float*)d_in[6];
    const float* bv   = (const float*)d_in[7];
    const float* W1   = (const float*)d_in[8];
    const float* b1   = (const float*)d_in[9];
    const float* W2   = (const float*)d_in[10];
    const float* b2   = (const float*)d_in[11];
    const float* ln_g = (const float*)d_in[12];
    const float* ln_b = (const float*)d_in[13];
    const int*   msk  = (const int*)d_in[14];

    float *Qb, *Kb, *Vb, *Ab, *Xb, *Hb;
    cudaGetSymbolAddress((void**)&Qb, g_Q);
    cudaGetSymbolAddress((void**)&Kb, g_K);
    cudaGetSymbolAddress((void**)&Vb, g_V);
    cudaGetSymbolAddress((void**)&Ab, g_att);
    cudaGetSymbolAddress((void**)&Xb, g_x);
    cudaGetSymbolAddress((void**)&Hb, g_h);

    // QKV projections: [4096,1024] @ [1024,1024]^T
    gemm_tc<0><<<dim3(DM / 128, MTOK / 128), 256>>>(q, Wq, bq, Qb, nullptr, MTOK, DM, DM);
    gemm_tc<0><<<dim3(DM / 128, MTOK / 128), 256>>>(k, Wk, bk, Kb, nullptr, MTOK, DM, DM);
    gemm_tc<0><<<dim3(DM / 128, MTOK / 128), 256>>>(k, Wv, bv, Vb, nullptr, MTOK, DM, DM);

    // causal attention
    attn_kernel<<<dim3(S_ / 128, H_, B_), 256>>>(Qb, Kb, Vb, Ab, msk);

    // residual + layernorm
    ln_kernel<<<MTOK, 256>>>(Ab, q, ln_g, ln_b, Xb);

    // FFN: gelu(x @ W1^T + b1) @ W2^T + b2 + x
    gemm_tc<1><<<dim3(DFF / 128, MTOK / 128), 256>>>(Xb, W1, b1, Hb, nullptr, MTOK, DFF, DM);
    gemm_tc<2><<<dim3(DM / 128, MTOK / 128), 256>>>(Hb, W2, b2, (float*)d_out, Xb, MTOK, DM, DFF);
}